// round 14
// baseline (speedup 1.0000x reference)
#include <cuda_runtime.h>
#include <cuda_fp16.h>
#include <cstdint>

// Problem constants
#define NB      32
#define CDIM    256
#define HWN     4096
#define KCODES  1024
#define N_VEC   (NB * HWN)        // 131072
#define N_ZQ    (NB * CDIM * HWN) // 33554432

#define MARGIN  1.5e-3f           // ~30 sigma of f16-filter dist error
#define CINF    3.4e38f

#define KC      8                 // k per B chunk
#define NCHUNK  (KCODES / 256 * CDIM / KC)   // 4 n-tiles x 32 = 128 chunks

// ---------------- static device scratch ----------------
__device__ uint32_t g_eh2[KCODES * CDIM];  // half2-dup codebook [nt][k][n'] (1 MB)
__device__ float    g_se[KCODES];          // ||e||^2 (exact fp32)
__device__ double   g_loss;

__device__ __forceinline__ uint32_t smem_u32(const void* p) {
    uint32_t a;
    asm("{ .reg .u64 t; cvta.to.shared.u64 t, %1; cvt.u32.u64 %0, t; }"
        : "=r"(a) : "l"(p));
    return a;
}
#define HFMA2(acc, a, b) \
    asm("fma.rn.f16x2 %0, %1, %2, %0;" : "+r"(acc) : "r"(a), "r"(b))
#define CP_ASYNC16(dst, src) \
    asm volatile("cp.async.cg.shared.global [%0], [%1], 16;" :: "r"(dst), "l"(src))
#define CP_COMMIT() asm volatile("cp.async.commit_group;" ::: "memory")
#define CP_WAIT(n)  asm volatile("cp.async.wait_group %0;" :: "n"(n) : "memory")

// ---------------------------------------------------------------------------
// Codebook prep: exact ||e||^2 + half2-dup pack [nt][k][n'], zero loss.
// ---------------------------------------------------------------------------
__global__ void cb_prep_kernel(const float* __restrict__ cb) {
    int n = blockIdx.x, t = threadIdx.x;
    float v = cb[n * CDIM + t];
    __half2 h2 = __floats2half2_rn(v, v);
    g_eh2[(n >> 8) * 65536 + t * 256 + (n & 255)] = *(uint32_t*)&h2;
    __shared__ float red[256];
    red[t] = __fmul_rn(v, v);
    __syncthreads();
    for (int s = 128; s > 0; s >>= 1) {
        if (t < s) red[t] = __fadd_rn(red[t], red[t + s]);
        __syncthreads();
    }
    if (t == 0) {
        g_se[n] = red[0];
        if (n == 0) g_loss = 0.0;
    }
}

// ---------------------------------------------------------------------------
// Fused main: HFMA2 f16 prefilter GEMM + margin filter + exact in-CTA
// rescore + sz + gather/loss/indices. 256 threads, 128 vecs x 1024 codes.
// ---------------------------------------------------------------------------
#define SM_ZS  0         // 131072 : z fp32 [256k][128m]
#define SM_ZH  131072    // 65536  : z half2 m-pairs [256k][64mp] (permuted)
#define SM_B   196608    // 3x8192 : B chunks [8k][256n'] half2-dup
#define SM_SE  221184    // 4096
#define SM_SZ  225280    // 512
#define SM_IDX 225792    // 512
#define SM_CNT 226304    // 32
#define SM_TOT 226336
// resolution overlay inside dead zH region after GEMM:
#define OV_RM    131072  // 128 x 33 f32
#define OV_GMIN  147968  // 512
#define OV_PAIR  148480  // 2048 u32
#define OV_KEY   156672  // 128 u64
#define OV_CNTM  157696  // 128 int
#define OV_OVF   158208  // 128 int
#define OV_LASTN 158720  // 128 int
#define OV_OVFL  159232  // 128 int

__global__ void __launch_bounds__(256, 1)
vq_main_kernel(const float* __restrict__ z, const float* __restrict__ cb,
               float* __restrict__ out, int mode) {
    extern __shared__ __align__(1024) float smf[];
    char* sm = (char*)smf;
    const uint32_t sb = smem_u32(sm);
    const int tid = threadIdx.x;
    const int w = tid >> 5, lane = tid & 31;
    const int s = lane >> 3;        // 0..3 (n sub-group)
    const int mc = lane & 7;        // 0..7 (m chunk)
    const int m0 = blockIdx.x * 128;
    const int b   = m0 >> 12;
    const int hw0 = m0 & (HWN - 1);

    float* zS  = smf;
    uint32_t* zH = (uint32_t*)(sm + SM_ZH);
    float* seS = (float*)(sm + SM_SE);
    float* szS = (float*)(sm + SM_SZ);
    int*   idxS = (int*)(sm + SM_IDX);

    for (int i = tid; i < KCODES; i += 256) seS[i] = g_se[i];

    // z tile: [256 k][128 m] fp32, coalesced
    for (int it = 0; it < 32; it++) {
        int idx = tid + it * 256;
        int c = idx >> 5, mq = idx & 31;
        float4 v = *(const float4*)(z + (((size_t)(b * CDIM + c)) << 12) + hw0 + (mq << 2));
        *(float4*)(zS + c * 128 + (mq << 2)) = v;
    }
    // prefetch B chunk 0 into buf 0 (8 KB)
#pragma unroll
    for (int it = 0; it < 2; it++) {
        int idx = tid * 2 + it;
        CP_ASYNC16(sb + SM_B + idx * 16, g_eh2 + idx * 4);
    }
    CP_COMMIT();
    __syncthreads();

    // sz (reference order: serial ascending c, unfused)
    if (tid < 128) {
        float a = 0.0f;
        for (int c = 0; c < CDIM; c++) {
            float x = zS[c * 128 + tid];
            a = __fadd_rn(a, __fmul_rn(x, x));
        }
        szS[tid] = a;
    }
    __syncthreads();

    // build zH: slot s2 = mc2*8+a2 holds m-pair mp = 2*mc2 + (a2&1) + (a2>>1)*16
    for (int it = 0; it < 64; it++) {
        int idx = tid + it * 256;
        int k = idx >> 6, s2 = idx & 63;
        int mc2 = s2 >> 3, a2 = s2 & 7;
        int mp = 2 * mc2 + (a2 & 1) + ((a2 >> 1) << 4);
        __half2 h2 = __floats2half2_rn(zS[k * 128 + 2 * mp], zS[k * 128 + 2 * mp + 1]);
        zH[k * 64 + s2] = *(uint32_t*)&h2;
    }

    // per-thread margin state: 16 rows (li = a*2+e), 1 slot each
    float rm[16], cd[16];
    int ci[16];
    unsigned ovfm = 0;
#pragma unroll
    for (int i = 0; i < 16; i++) { rm[i] = CINF; cd[i] = CINF; ci[i] = 0; }

    uint32_t acc[64];
#pragma unroll
    for (int i = 0; i < 64; i++) acc[i] = 0u;   // f16x2 (+0,+0)

    __syncthreads();

    // GEMM: 128 chunks = 4 n-tiles x 32 k-chunks (KC=8), 3-buffer pipeline
    for (int cidx = 0; cidx < NCHUNK; cidx++) {
        if (cidx + 1 < NCHUNK) {
            const uint32_t* src = g_eh2 + (size_t)((cidx + 1) >> 5) * 65536
                                        + (size_t)((cidx + 1) & 31) * (KC * 256);
            uint32_t dst = sb + SM_B + ((cidx + 1) % 3) * 8192;
#pragma unroll
            for (int it = 0; it < 2; it++) {
                int idx = tid * 2 + it;
                CP_ASYNC16(dst + idx * 16, src + idx * 4);
            }
            CP_COMMIT();
            CP_WAIT(1);   // chunk cidx landed (cidx+1 in flight)
        } else {
            CP_WAIT(0);
        }
        __syncthreads();  // chunk visible; 3 buffers -> one sync is hazard-free

        const uint32_t* bT = (const uint32_t*)(sm + SM_B + (cidx % 3) * 8192);
        const int kbase = (cidx & 31) * KC;
#pragma unroll 4
        for (int kk = 0; kk < KC; kk++) {
            const uint32_t* Ap = zH + (kbase + kk) * 64 + mc * 8;
            uint4 a0 = *(const uint4*)Ap;
            uint4 a1 = *(const uint4*)(Ap + 4);
            const uint32_t* Bp = bT + kk * 256 + w * 32 + s * 8;
            uint4 b0 = *(const uint4*)Bp;
            uint4 b1 = *(const uint4*)(Bp + 4);
            uint32_t av[8] = {a0.x, a0.y, a0.z, a0.w, a1.x, a1.y, a1.z, a1.w};
            uint32_t bv[8] = {b0.x, b0.y, b0.z, b0.w, b1.x, b1.y, b1.z, b1.w};
#pragma unroll
            for (int a = 0; a < 8; a++)
#pragma unroll
                for (int c = 0; c < 8; c++)
                    HFMA2(acc[a * 8 + c], av[a], bv[c]);
        }

        if ((cidx & 31) == 31) {
            // epilogue for n-tile nt: approx dist + 1-slot margin update
            const int nt = cidx >> 5;
#pragma unroll
            for (int ni = 0; ni < 8; ni++) {
                const int n = nt * 256 + w * 32 + s * 8 + ni;
                const float se = seS[n];
#pragma unroll
                for (int a = 0; a < 8; a++) {
                    uint32_t u = acc[a * 8 + ni];
                    __half2 h2 = *reinterpret_cast<__half2*>(&u);
                    float2 f2 = __half22float2(h2);
                    const int mp = 2 * mc + (a & 1) + ((a >> 1) << 4);
#pragma unroll
                    for (int e = 0; e < 2; e++) {
                        const int li = a * 2 + e;
                        const int m = 2 * mp + e;
                        float dot = (e == 0) ? f2.x : f2.y;
                        float d = szS[m] + se - 2.0f * dot;
                        if (d < rm[li] + MARGIN) {
                            rm[li] = fminf(rm[li], d);
                            if (!(ovfm & (1u << li))) {
                                bool oldlive = (cd[li] < rm[li] + MARGIN);
                                if (!oldlive) { cd[li] = d; ci[li] = n; }
                                else ovfm |= (1u << li);   // two live -> full scan
                            }
                        }
                    }
                }
            }
#pragma unroll
            for (int i = 0; i < 64; i++) acc[i] = 0u;
        }
    }
    __syncthreads();

    // ---- resolution (R11-proven flow, 32 partials/row, 1 slot/thread) ----
    float* RMS   = (float*)(sm + OV_RM);            // [128][33]
    float* gminS = (float*)(sm + OV_GMIN);
    uint32_t* pairs = (uint32_t*)(sm + OV_PAIR);
    unsigned long long* keyS = (unsigned long long*)(sm + OV_KEY);
    int* cntmS  = (int*)(sm + OV_CNTM);
    int* ovfS   = (int*)(sm + OV_OVF);
    int* lastnS = (int*)(sm + OV_LASTN);
    int* ovflS  = (int*)(sm + OV_OVFL);
    int* cnt2   = (int*)(sm + SM_CNT);

    if (tid < 128) { cntmS[tid] = 0; ovfS[tid] = 0; keyS[tid] = ~0ull; lastnS[tid] = 0; }
    if (tid == 0) { cnt2[0] = 0; cnt2[1] = 0; }
    __syncthreads();

    const int pid = w * 4 + s;
#pragma unroll
    for (int li = 0; li < 16; li++) {
        const int mp = 2 * mc + ((li >> 1) & 1) + ((li >> 2) << 4);
        const int m = 2 * mp + (li & 1);
        RMS[m * 33 + pid] = rm[li];
        if (ovfm & (1u << li)) atomicOr(&ovfS[m], 1);
    }
    __syncthreads();

    if (tid < 128) {
        float gm = CINF;
#pragma unroll 8
        for (int p = 0; p < 32; p++) gm = fminf(gm, RMS[tid * 33 + p]);
        gminS[tid] = gm;
    }
    __syncthreads();

#pragma unroll
    for (int li = 0; li < 16; li++) {
        const int mp = 2 * mc + ((li >> 1) & 1) + ((li >> 2) << 4);
        const int m = 2 * mp + (li & 1);
        if (ovfS[m]) continue;
        if (cd[li] < gminS[m] + MARGIN) {
            int p = atomicAdd(&cnt2[0], 1);
            if (p < 2048) {
                pairs[p] = (uint32_t)((m << 10) | ci[li]);
                atomicAdd(&cntmS[m], 1);
                lastnS[m] = ci[li];
            } else atomicExch(&ovfS[m], 1);
        }
    }
    __syncthreads();

    if (tid < 128) {
        if (ovfS[tid] || cntmS[tid] == 0) {
            int o = atomicAdd(&cnt2[1], 1);
            ovflS[o] = tid;
        } else if (cntmS[tid] == 1) {
            idxS[tid] = lastnS[tid];
        }
    }
    __syncthreads();

    // exact pair rescore (bitwise reference recipe)
    const int np = min(cnt2[0], 2048);
    for (int p = tid; p < np; p += 256) {
        uint32_t e = pairs[p];
        int m = e >> 10, n = e & 1023;
        if (ovfS[m] || cntmS[m] == 1) continue;
        const float* er = cb + (size_t)n * CDIM;
        float a2 = 0.0f;
#pragma unroll 16
        for (int k = 0; k < CDIM; k++) a2 = __fmaf_rn(zS[k * 128 + m], __ldg(er + k), a2);
        float d = __fsub_rn(__fadd_rn(szS[m], seS[n]), __fmul_rn(2.0f, a2));
        unsigned long long kk = ((unsigned long long)__float_as_uint(d) << 32) | (unsigned)n;
        atomicMin(&keyS[m], kk);
    }

    // exact full rescan for overflow rows (warp per row)
    const int novf = cnt2[1];
    for (int o = w; o < novf; o += 8) {
        int row = ovflS[o];
        float sz = szS[row];
        float bd = __int_as_float(0x7f800000);
        int bi = 0x7fffffff;
        for (int c = lane; c < KCODES; c += 32) {
            const float* er = cb + (size_t)c * CDIM;
            float a2 = 0.0f;
#pragma unroll 16
            for (int k = 0; k < CDIM; k++) a2 = __fmaf_rn(zS[k * 128 + row], __ldg(er + k), a2);
            float d = __fsub_rn(__fadd_rn(sz, seS[c]), __fmul_rn(2.0f, a2));
            if (d < bd) { bd = d; bi = c; }   // ascending c: strict < keeps lowest
        }
#pragma unroll
        for (int off = 16; off > 0; off >>= 1) {
            float od = __shfl_xor_sync(0xffffffffu, bd, off);
            int   oi = __shfl_xor_sync(0xffffffffu, bi, off);
            if (od < bd || (od == bd && oi < bi)) { bd = od; bi = oi; }
        }
        if (lane == 0) idxS[row] = bi;
    }
    __syncthreads();

    if (tid < 128 && !ovfS[tid] && cntmS[tid] >= 2)
        idxS[tid] = (int)(keyS[tid] & 0xffffffffu);
    __syncthreads();

    if (mode >= 2 && tid < 128)
        out[N_ZQ + 2 + m0 + tid] = (float)idxS[tid];

    // ---- fused gather: z from smem, e from L2, coalesced stores ----
    {
        const int gm = tid & 127, gh = tid >> 7;   // row, column-half
        const int idx = idxS[gm];
        const float4* er4 = (const float4*)(cb + (size_t)idx * CDIM) + gh * 32;
        float lsum = 0.0f;
#pragma unroll 4
        for (int cq = 0; cq < 32; cq++) {
            float4 e4 = er4[cq];
            int c0 = gh * 128 + cq * 4;
            float ev[4] = {e4.x, e4.y, e4.z, e4.w};
#pragma unroll
            for (int j = 0; j < 4; j++) {
                int c = c0 + j;
                float zv = zS[c * 128 + gm];
                float t  = __fsub_rn(ev[j], zv);           // e - z
                out[(((size_t)(b * CDIM + c)) << 12) + hw0 + gm] = __fadd_rn(zv, t);
                lsum = __fmaf_rn(t, t, lsum);
            }
        }
        for (int o = 16; o > 0; o >>= 1)
            lsum += __shfl_down_sync(0xffffffffu, lsum, o);
        if (lane == 0) atomicAdd(&g_loss, (double)lsum);
    }
}

__global__ void finalize_kernel(float* __restrict__ out, int mode) {
    if (mode >= 1) {
        float mean = (float)(g_loss / (double)N_ZQ);
        out[N_ZQ]     = mean;          // codebook_loss
        out[N_ZQ + 1] = 0.25f * mean;  // commitment_loss = exactly 0.25 * mean
    }
}

// ---------------------------------------------------------------------------
extern "C" void kernel_launch(void* const* d_in, const int* in_sizes, int n_in,
                              void* d_out, int out_size) {
    const float* z  = (const float*)d_in[0];
    const float* cb = (const float*)d_in[1];
    float* out = (float*)d_out;

    int mode = 0;
    if (out_size >= N_ZQ + 2) mode = 1;
    if (out_size >= N_ZQ + 2 + N_VEC) mode = 2;

    cudaFuncSetAttribute(vq_main_kernel,
                         cudaFuncAttributeMaxDynamicSharedMemorySize, SM_TOT);

    cb_prep_kernel<<<KCODES, 256>>>(cb);
    vq_main_kernel<<<N_VEC / 128, 256, SM_TOT>>>(z, cb, out, mode);
    finalize_kernel<<<1, 1>>>(out, mode);
}

// round 15
// speedup vs baseline: 39.9155x; 39.9155x over previous
#include <cuda_runtime.h>
#include <cuda_fp16.h>
#include <cstdint>

// Problem constants
#define NB      32
#define CDIM    256
#define HWN     4096
#define KCODES  1024
#define N_VEC   (NB * HWN)        // 131072
#define N_ZQ    (NB * CDIM * HWN) // 33554432

#define MARGIN  1.0e-3f           // ~25 sigma of filter dist error
#define NT      128               // codes per n-tile
#define NTILES  8
#define KC      8                 // k per B chunk
#define CPT     32                // chunks per tile
#define NCHUNK  (NTILES * CPT)    // 256

// ---------------- static device scratch ----------------
__device__ uint32_t g_eh2[KCODES * CDIM];  // half2-dup codebook [tile][k][n'] (1 MB)
__device__ float    g_se[KCODES];          // ||e||^2 (exact fp32)
__device__ double   g_loss;

__device__ __forceinline__ uint32_t smem_u32(const void* p) {
    uint32_t a;
    asm("{ .reg .u64 t; cvta.to.shared.u64 t, %1; cvt.u32.u64 %0, t; }"
        : "=r"(a) : "l"(p));
    return a;
}
#define HFMA2(acc, a, b) \
    asm("fma.rn.f16x2 %0, %1, %2, %0;" : "+r"(acc) : "r"(a), "r"(b))
#define CP_ASYNC16(dst, src) \
    asm volatile("cp.async.cg.shared.global [%0], [%1], 16;" :: "r"(dst), "l"(src))
#define CP_COMMIT() asm volatile("cp.async.commit_group;" ::: "memory")
#define CP_WAIT(n)  asm volatile("cp.async.wait_group %0;" :: "n"(n) : "memory")

// ---------------------------------------------------------------------------
// Codebook prep: exact ||e||^2 + half2-dup pack [tile][k][n'], zero loss.
// ---------------------------------------------------------------------------
__global__ void cb_prep_kernel(const float* __restrict__ cb) {
    int n = blockIdx.x, t = threadIdx.x;
    float v = cb[n * CDIM + t];
    __half2 h2 = __floats2half2_rn(v, v);
    g_eh2[(n >> 7) * 32768 + t * NT + (n & 127)] = *(uint32_t*)&h2;
    __shared__ float red[256];
    red[t] = __fmul_rn(v, v);
    __syncthreads();
    for (int s = 128; s > 0; s >>= 1) {
        if (t < s) red[t] = __fadd_rn(red[t], red[t + s]);
        __syncthreads();
    }
    if (t == 0) {
        g_se[n] = red[0];
        if (n == 0) g_loss = 0.0;
    }
}

// ---------------------------------------------------------------------------
// Fused main: HFMA2 prefilter GEMM (branch-free, smem-dist dump) + smem
// margin scan + exact in-CTA rescore + sz + gather/loss/indices.
// 256 threads, 128 vecs x 1024 codes per CTA.
// Thread: mc = lane&7 -> m 16mc..16mc+15 (m-pairs mp = 8mc..8mc+7);
//         n = w*16 + (lane>>3)*4 + ni.
// ---------------------------------------------------------------------------
#define SM_ZH   0        // 65536 : z f16 m-pairs [256k][64mp]
#define SM_D    65536    // 66048 : dists [128m][129] f32; staging overlay later
#define SM_B    131584   // 3x4096 : B chunks [8k][128n] half2-dup
#define SM_SE   143872   // 4096
#define SM_SZ   147968   // 512
#define SM_CD   148480   // 2048 (128 rows x 4 slots)
#define SM_CI   150528   // 2048
#define SM_IDX  152576   // 512
#define SM_PEND 153088   // 512
#define SM_RSLT 153600   // 512 : row -> stage slot
#define SM_SROW 154112   // 256 : slot -> row (64 slots)
#define SM_PAIR 154368   // 2048 (512 pairs max = 128x4)
#define SM_OVFL 156416   // 512
#define SM_KEY  156928   // 1024 (128 u64)
#define SM_CNT  157952   // 32
#define SM_TOT  157984

__global__ void __launch_bounds__(256, 1)
vq_main_kernel(const float* __restrict__ z, const float* __restrict__ cb,
               float* __restrict__ out, int mode) {
    extern __shared__ __align__(1024) float smf[];
    char* sm = (char*)smf;
    const uint32_t sb = smem_u32(sm);
    const int tid = threadIdx.x;
    const int w = tid >> 5, lane = tid & 31;
    const int mc = lane & 7;        // m chunk
    const int s  = lane >> 3;       // n sub-group 0..3
    const int m0 = blockIdx.x * 128;
    const int b   = m0 >> 12;
    const int hw0 = m0 & (HWN - 1);

    uint32_t* zH = (uint32_t*)(sm + SM_ZH);
    float* D   = (float*)(sm + SM_D);
    float* seS = (float*)(sm + SM_SE);
    float* szS = (float*)(sm + SM_SZ);
    float* cdS = (float*)(sm + SM_CD);
    int*   ciS = (int*)(sm + SM_CI);
    int*   idxS = (int*)(sm + SM_IDX);

    // prefetch B chunk 0 early
    CP_ASYNC16(sb + SM_B + tid * 16, g_eh2 + tid * 4);
    CP_COMMIT();

    for (int i = tid; i < KCODES; i += 256) seS[i] = g_se[i];

    // build zH: [k][mp] f16 pairs (coalesced float2 reads)
    for (int it = 0; it < 64; it++) {
        int idx = tid + it * 256;
        int k = idx >> 6, mp = idx & 63;
        float2 v = *(const float2*)(z + (((size_t)(b * CDIM + k)) << 12) + hw0 + 2 * mp);
        __half2 h2 = __floats2half2_rn(v.x, v.y);
        zH[k * 64 + mp] = *(uint32_t*)&h2;
    }

    // sz: reference order (serial ascending c, unfused), coalesced across rows
    if (tid < 128) {
        float a = 0.0f;
#pragma unroll 8
        for (int c = 0; c < CDIM; c++) {
            float x = z[(((size_t)(b * CDIM + c)) << 12) + hw0 + tid];
            a = __fadd_rn(a, __fmul_rn(x, x));
        }
        szS[tid] = a;
    }

    // per-row scan state (owner thread tid<128): runmin + cnt in regs
    float runmin = 3.4e38f;
    int cnt = 0;

    uint32_t acc[32];
    float facc[64];
#pragma unroll
    for (int i = 0; i < 32; i++) acc[i] = 0u;
#pragma unroll
    for (int i = 0; i < 64; i++) facc[i] = 0.0f;

    __syncthreads();

    // ---- GEMM: 256 chunk-iters = 8 tiles x 32 k-chunks ----
    for (int cidx = 0; cidx < NCHUNK; cidx++) {
        if (cidx + 1 < NCHUNK) {
            const uint32_t* src = g_eh2 + (size_t)((cidx + 1) >> 5) * 32768
                                        + (size_t)((cidx + 1) & 31) * 1024;
            CP_ASYNC16(sb + SM_B + ((cidx + 1) % 3) * 4096 + tid * 16, src + tid * 4);
            CP_COMMIT();
            CP_WAIT(1);
        } else {
            CP_WAIT(0);
        }
        __syncthreads();

        const uint32_t* bT = (const uint32_t*)(sm + SM_B + (cidx % 3) * 4096);
        const int ch = cidx & 31;
#pragma unroll
        for (int kk = 0; kk < KC; kk++) {
            const uint32_t* Ap = zH + (ch * KC + kk) * 64 + mc * 8;
            uint4 a0 = *(const uint4*)Ap;
            uint4 a1 = *(const uint4*)(Ap + 4);
            uint4 b0 = *(const uint4*)(bT + kk * NT + w * 16 + s * 4);
            uint32_t av[8] = {a0.x, a0.y, a0.z, a0.w, a1.x, a1.y, a1.z, a1.w};
            uint32_t bv[4] = {b0.x, b0.y, b0.z, b0.w};
#pragma unroll
            for (int mp = 0; mp < 8; mp++)
#pragma unroll
                for (int ni = 0; ni < 4; ni++)
                    HFMA2(acc[mp * 4 + ni], av[mp], bv[ni]);
        }

        if ((ch & 7) == 7) {
            // flush f16 partials (64 k) into f32 accumulators — branch-free
#pragma unroll
            for (int mp = 0; mp < 8; mp++)
#pragma unroll
                for (int ni = 0; ni < 4; ni++) {
                    uint32_t u = acc[mp * 4 + ni];
                    float2 f = __half22float2(*reinterpret_cast<__half2*>(&u));
                    facc[mp * 8 + ni]     += f.x;
                    facc[mp * 8 + 4 + ni] += f.y;
                    acc[mp * 4 + ni] = 0u;
                }
        }

        if (ch == 31) {
            // dump dots for this tile to D, reset facc
#pragma unroll
            for (int mp = 0; mp < 8; mp++)
#pragma unroll
                for (int e = 0; e < 2; e++)
#pragma unroll
                    for (int ni = 0; ni < 4; ni++) {
                        int row = 16 * mc + 2 * mp + e;
                        D[row * 129 + w * 16 + s * 4 + ni] = facc[mp * 8 + e * 4 + ni];
                        facc[mp * 8 + e * 4 + ni] = 0.0f;
                    }
            __syncthreads();

            // margin scan (smem arrays, branchy but outside unrolled GEMM)
            if (tid < 128) {
                const int nt = cidx >> 5;
                const int n0 = nt * NT;
                const float szr = szS[tid];
                float* cd = cdS + tid * 4;
                int*   ci = ciS + tid * 4;
                for (int j = 0; j < NT; j++) {
                    float d = szr + seS[n0 + j] - 2.0f * D[tid * 129 + j];
                    if (d < runmin + MARGIN) {
                        runmin = fminf(runmin, d);
                        if (cnt < 4) { cd[cnt] = d; ci[cnt] = n0 + j; cnt++; }
                        else if (cnt == 4) {
                            int w2 = 0;
                            for (int t = 0; t < 4; t++)
                                if (cd[t] < runmin + MARGIN) { cd[w2] = cd[t]; ci[w2] = ci[t]; w2++; }
                            cnt = w2;
                            if (cnt < 4) { cd[cnt] = d; ci[cnt] = n0 + j; cnt++; }
                            else cnt = 5;  // overflow sentinel
                        }
                    }
                }
            }
            // next iteration's top sync orders scan-done vs future D writes
        }
    }
    __syncthreads();

    // ---- resolution ----
    int* pendS = (int*)(sm + SM_PEND);
    int* rsltS = (int*)(sm + SM_RSLT);
    int* srowS = (int*)(sm + SM_SROW);
    uint32_t* pairS = (uint32_t*)(sm + SM_PAIR);
    int* ovflS = (int*)(sm + SM_OVFL);
    unsigned long long* keyS = (unsigned long long*)(sm + SM_KEY);
    int* cnt3 = (int*)(sm + SM_CNT);   // [0]=npairs [1]=novf [2]=nslots

    if (tid < 128) { pendS[tid] = 0; keyS[tid] = ~0ull; }
    if (tid == 0) { cnt3[0] = 0; cnt3[1] = 0; cnt3[2] = 0; }
    __syncthreads();

    if (tid < 128) {
        const int row = tid;
        int u = 0, uc[4];
        if (cnt <= 4) {
            for (int t = 0; t < cnt; t++)
                if (cdS[row * 4 + t] < runmin + MARGIN) uc[u++] = ciS[row * 4 + t];
        }
        if (cnt > 4 || u == 0) {
            int sl = atomicAdd(&cnt3[2], 1);
            rsltS[row] = (sl < 64) ? sl : -1;
            if (sl < 64) srowS[sl] = row;
            int o = atomicAdd(&cnt3[1], 1);
            ovflS[o] = row;
            pendS[row] = 2;
        } else if (u == 1) {
            idxS[row] = uc[0];
        } else {
            pendS[row] = 1;
            int sl = atomicAdd(&cnt3[2], 1);
            rsltS[row] = (sl < 64) ? sl : -1;
            if (sl < 64) srowS[sl] = row;
            for (int t = 0; t < u; t++) {
                int p = atomicAdd(&cnt3[0], 1);   // <= 512 total by construction
                pairS[p] = (uint32_t)((row << 10) | uc[t]);
            }
        }
    }
    __syncthreads();

    // stage fp32 z rows for ambiguous rows into D region
    float* stage = D;
    const int nslots = min(cnt3[2], 64);
    for (int i = tid; i < nslots * CDIM; i += 256) {
        int sl = i >> 8, c = i & 255;
        stage[sl * CDIM + c] = z[(((size_t)(b * CDIM + c)) << 12) + hw0 + srowS[sl]];
    }
    __syncthreads();

    // exact pair rescore (bitwise reference recipe)
    const int np = cnt3[0];
    for (int p = tid; p < np; p += 256) {
        uint32_t e = pairS[p];
        int row = e >> 10, n = e & 1023;
        const float* er = cb + (size_t)n * CDIM;
        int sl = rsltS[row];
        float a2 = 0.0f;
        if (sl >= 0) {
            const float* zs = stage + sl * CDIM;
#pragma unroll 16
            for (int k = 0; k < CDIM; k++) a2 = __fmaf_rn(zs[k], __ldg(er + k), a2);
        } else {
            for (int k = 0; k < CDIM; k++)
                a2 = __fmaf_rn(z[(((size_t)(b * CDIM + k)) << 12) + hw0 + row],
                               __ldg(er + k), a2);
        }
        float d = __fsub_rn(__fadd_rn(szS[row], seS[n]), __fmul_rn(2.0f, a2));
        unsigned long long kk = ((unsigned long long)__float_as_uint(d) << 32) | (unsigned)n;
        atomicMin(&keyS[row], kk);
    }

    // exact full rescan for overflow rows (warp per row)
    const int novf = cnt3[1];
    for (int o = w; o < novf; o += 8) {
        int row = ovflS[o];
        int sl = rsltS[row];
        float sz = szS[row];
        float bd = __int_as_float(0x7f800000);
        int bi = 0x7fffffff;
        for (int c = lane; c < KCODES; c += 32) {
            const float* er = cb + (size_t)c * CDIM;
            float a2 = 0.0f;
            if (sl >= 0) {
                const float* zs = stage + sl * CDIM;
#pragma unroll 16
                for (int k = 0; k < CDIM; k++) a2 = __fmaf_rn(zs[k], __ldg(er + k), a2);
            } else {
                for (int k = 0; k < CDIM; k++)
                    a2 = __fmaf_rn(z[(((size_t)(b * CDIM + k)) << 12) + hw0 + row],
                                   __ldg(er + k), a2);
            }
            float d = __fsub_rn(__fadd_rn(sz, seS[c]), __fmul_rn(2.0f, a2));
            if (d < bd) { bd = d; bi = c; }   // ascending c: strict < keeps lowest
        }
#pragma unroll
        for (int off = 16; off > 0; off >>= 1) {
            float od = __shfl_xor_sync(0xffffffffu, bd, off);
            int   oi = __shfl_xor_sync(0xffffffffu, bi, off);
            if (od < bd || (od == bd && oi < bi)) { bd = od; bi = oi; }
        }
        if (lane == 0) idxS[row] = bi;
    }
    __syncthreads();

    if (tid < 128 && pendS[tid] == 1)
        idxS[tid] = (int)(keyS[tid] & 0xffffffffu);
    __syncthreads();

    if (mode >= 2 && tid < 128)
        out[N_ZQ + 2 + m0 + tid] = (float)idxS[tid];

    // ---- fused gather: z from GMEM (coalesced), e from L2 ----
    {
        const int gm = tid & 127, gh = tid >> 7;   // row, column-half
        const int idx = idxS[gm];
        const float4* er4 = (const float4*)(cb + (size_t)idx * CDIM) + gh * 32;
        float lsum = 0.0f;
#pragma unroll 4
        for (int cq = 0; cq < 32; cq++) {
            float4 e4 = er4[cq];
            int c0 = gh * 128 + cq * 4;
            float ev[4] = {e4.x, e4.y, e4.z, e4.w};
#pragma unroll
            for (int j = 0; j < 4; j++) {
                int c = c0 + j;
                size_t zi = (((size_t)(b * CDIM + c)) << 12) + hw0 + gm;
                float zv = z[zi];
                float t  = __fsub_rn(ev[j], zv);           // e - z
                out[zi]  = __fadd_rn(zv, t);               // z + (e - z)
                lsum = __fmaf_rn(t, t, lsum);
            }
        }
        for (int o = 16; o > 0; o >>= 1)
            lsum += __shfl_down_sync(0xffffffffu, lsum, o);
        if (lane == 0) atomicAdd(&g_loss, (double)lsum);
    }
}

__global__ void finalize_kernel(float* __restrict__ out, int mode) {
    if (mode >= 1) {
        float mean = (float)(g_loss / (double)N_ZQ);
        out[N_ZQ]     = mean;          // codebook_loss
        out[N_ZQ + 1] = 0.25f * mean;  // commitment_loss = exactly 0.25 * mean
    }
}

// ---------------------------------------------------------------------------
extern "C" void kernel_launch(void* const* d_in, const int* in_sizes, int n_in,
                              void* d_out, int out_size) {
    const float* z  = (const float*)d_in[0];
    const float* cb = (const float*)d_in[1];
    float* out = (float*)d_out;

    int mode = 0;
    if (out_size >= N_ZQ + 2) mode = 1;
    if (out_size >= N_ZQ + 2 + N_VEC) mode = 2;

    cudaFuncSetAttribute(vq_main_kernel,
                         cudaFuncAttributeMaxDynamicSharedMemorySize, SM_TOT);

    cb_prep_kernel<<<KCODES, 256>>>(cb);
    vq_main_kernel<<<N_VEC / 128, 256, SM_TOT>>>(z, cb, out, mode);
    finalize_kernel<<<1, 1>>>(out, mode);
}

// round 17
// speedup vs baseline: 78.9209x; 1.9772x over previous
#include <cuda_runtime.h>
#include <cuda_fp16.h>
#include <cstdint>

// Problem constants
#define NB      32
#define CDIM    256
#define HWN     4096
#define KCODES  1024
#define N_VEC   (NB * HWN)        // 131072
#define N_ZQ    (NB * CDIM * HWN) // 33554432

#define MARGIN  1.0e-3f
#define FINF    __int_as_float(0x7f800000)

// ---------------- static device scratch ----------------
__device__ __half g_ehB[KCODES * CDIM];    // f16 codebook, SW128 chunk blocks (512 KB)
__device__ float  g_er2[KCODES * CDIM];    // fp32 rescan codebook, interleaved (1 MB)
__device__ float  g_se[KCODES];            // ||e||^2 (exact fp32)
__device__ double g_loss;

// ---------------- helpers ----------------
__device__ __forceinline__ uint32_t smem_u32(const void* p) {
    uint32_t a;
    asm("{ .reg .u64 t; cvta.to.shared.u64 t, %1; cvt.u32.u64 %0, t; }"
        : "=r"(a) : "l"(p));
    return a;
}
#define SW128(x) ((uint32_t)(x) ^ ((((uint32_t)(x)) >> 3) & 0x70u))

__device__ __forceinline__ void ldsm4(uint32_t* r, uint32_t addr) {
    asm volatile("ldmatrix.sync.aligned.m8n8.x4.shared.b16 {%0,%1,%2,%3}, [%4];"
                 : "=r"(r[0]), "=r"(r[1]), "=r"(r[2]), "=r"(r[3]) : "r"(addr));
}
__device__ __forceinline__ void mma16816(float* c, const uint32_t* a,
                                         uint32_t b0, uint32_t b1) {
    asm volatile("mma.sync.aligned.m16n8k16.row.col.f32.f16.f16.f32 "
                 "{%0,%1,%2,%3}, {%4,%5,%6,%7}, {%8,%9}, {%0,%1,%2,%3};"
                 : "+f"(c[0]), "+f"(c[1]), "+f"(c[2]), "+f"(c[3])
                 : "r"(a[0]), "r"(a[1]), "r"(a[2]), "r"(a[3]), "r"(b0), "r"(b1));
}
__device__ __forceinline__ unsigned long long dup2(float x) {
    unsigned long long r;
    unsigned u = __float_as_uint(x);
    asm("mov.b64 %0, {%1, %2};" : "=l"(r) : "r"(u), "r"(u));
    return r;
}
#define FMA2(acc, a, b) \
    asm("fma.rn.f32x2 %0, %1, %2, %0;" : "+l"(acc) : "l"(a), "l"(b))
#define CP_ASYNC16(dst, src) \
    asm volatile("cp.async.cg.shared.global [%0], [%1], 16;" :: "r"(dst), "l"(src))
#define CP_COMMIT() asm volatile("cp.async.commit_group;" ::: "memory")
#define CP_WAIT(n)  asm volatile("cp.async.wait_group %0;" :: "n"(n) : "memory")

// ---------------------------------------------------------------------------
// Codebook prep: exact ||e||^2 + f16 SW128 chunk blocks + fp32 interleaved
// rescan layout, zero loss.
// ---------------------------------------------------------------------------
__global__ void cb_prep_kernel(const float* __restrict__ cb) {
    int n = blockIdx.x, k = threadIdx.x;
    float v = cb[n * CDIM + k];
    // f16 SW128 block: tile t=n>>7, k-chunk c=k>>6, 16KB blocks of [128n][64k]
    {
        int t = n >> 7, c = k >> 6;
        uint32_t off = ((uint32_t)(t * 4 + c) << 14) +
                       SW128((uint32_t)((n & 127) * 128 + (k & 63) * 2));
        *(__half*)((char*)g_ehB + off) = __float2half(v);
    }
    // fp32 rescan layout (distinct-interleaved): block (t2*4+c2)*4096 + kl*64 + nl
    // consumer u64 at pair*2 = codes (t2*64 + 2*pair, +1)
    {
        int t2 = n >> 6, nl = n & 63, c2 = k >> 6, kl = k & 63;
        g_er2[(t2 * 4 + c2) * 4096 + kl * 64 + nl] = v;
    }
    __shared__ float red[256];
    red[k] = __fmul_rn(v, v);
    __syncthreads();
    for (int s = 128; s > 0; s >>= 1) {
        if (k < s) red[k] = __fadd_rn(red[k], red[k + s]);
        __syncthreads();
    }
    if (k == 0) {
        g_se[n] = red[0];
        if (n == 0) g_loss = 0.0;
    }
}

// ---------------------------------------------------------------------------
// Main kernel: HMMA f16 prefilter GEMM (branch-free min1/min2 epilogue) +
// margin flag + in-CTA exact f32x2 rescan + gather/loss/indices.
// 512 threads (16 warps, 4m x 4n), 128 vecs x 1024 codes per CTA.
// ---------------------------------------------------------------------------
#define SM_ZH   0        // 65536 : z f16 [128m][256k] as 4 SW128 chunks
#define SM_B    65536    // 2 x 16384 : B chunks [128n][64k] SW128
#define SM_SE   98304    // 4096
#define SM_MS1  102400   // 128 x 17 f32
#define SM_MS2  111104   // 128 x 17 f32
#define SM_MI1  119808   // 128 x 17 i32
#define SM_IDX  128512   // 512
#define SM_FLG  129024   // 512
#define SM_CNT  129536   // 32
#define SM_TOT  129568
// overlays inside SM_ZH after GEMM:
#define OV_ZST  0        // 16 x 256 f32 staged z rows (16384)
#define OV_SZ   16384    // 16 f32
#define OV_BB   16448    // 16384 : rescan B block [64k][64n] f32
#define OV_PB   32832    // 16 x 32 u64 partials (4096)

__global__ void __launch_bounds__(512, 1)
vq_main_kernel(const float* __restrict__ z, const float* __restrict__ cb,
               float* __restrict__ out, int mode) {
    extern __shared__ __align__(1024) float smf[];
    char* sm = (char*)smf;
    const uint32_t sb = smem_u32(sm);
    const int tid = threadIdx.x;
    const int wid = tid >> 5, lane = tid & 31;
    const int wm = wid >> 2, wn = wid & 3;
    const int m0 = blockIdx.x * 128;
    const int b   = m0 >> 12;
    const int hw0 = m0 & (HWN - 1);

    float* seS = (float*)(sm + SM_SE);
    int*   idxS = (int*)(sm + SM_IDX);

    for (int i = tid; i < KCODES; i += 512) seS[i] = g_se[i];

    // ---- Phase 1: z -> f16 SW128 chunks via through-smem transpose ----
    float* stg = (float*)(sm + SM_B);   // staging [64 c][128 m] fp32
    for (int p = 0; p < 4; p++) {
        if (p > 0) __syncthreads();
#pragma unroll
        for (int it = 0; it < 4; it++) {
            int idx = tid + it * 512;
            int cl = idx >> 5, mq = idx & 31;
            float4 v = *(const float4*)(z +
                (((size_t)(b * CDIM + p * 64 + cl)) << 12) + hw0 + (mq << 2));
            *(float4*)(stg + cl * 128 + (mq << 2)) = v;
        }
        __syncthreads();
#pragma unroll
        for (int it = 0; it < 2; it++) {
            int task = tid + it * 512;
            int m = task & 127, g8 = task >> 7;
            uint32_t u[4];
#pragma unroll
            for (int q = 0; q < 4; q++) {
                __half2 h2 = __floats2half2_rn(stg[(g8 * 8 + q * 2) * 128 + m],
                                               stg[(g8 * 8 + q * 2 + 1) * 128 + m]);
                u[q] = *(uint32_t*)&h2;
            }
            *(uint4*)(sm + SM_ZH + p * 16384 + SW128(m * 128 + g8 * 16)) =
                make_uint4(u[0], u[1], u[2], u[3]);
        }
    }
    __syncthreads();

    // prefetch B chunk 0 (16 KB; SW128 baked into global layout)
    CP_ASYNC16(sb + SM_B + tid * 32,      (const char*)g_ehB + tid * 32);
    CP_ASYNC16(sb + SM_B + tid * 32 + 16, (const char*)g_ehB + tid * 32 + 16);
    CP_COMMIT();

    const int q = lane >> 3, lr = lane & 7;
    const int arow = wm * 32 + ((q & 1) << 3) + lr;
    const int acol = (q >> 1) << 4;
    const int brow = wn * 32 + ((q >> 1) << 3) + lr;
    const int bcol = (q & 1) << 4;
    const int g = lane >> 2, tg = lane & 3;

    float acc[2][4][4];
#pragma unroll
    for (int a = 0; a < 2; a++)
#pragma unroll
        for (int c = 0; c < 4; c++)
#pragma unroll
            for (int e = 0; e < 4; e++) acc[a][c][e] = 0.0f;

    float ms1[4], ms2[4];
    int   mi1[4];
#pragma unroll
    for (int i = 0; i < 4; i++) { ms1[i] = FINF; ms2[i] = FINF; mi1[i] = 0x7fffffff; }

    // ---- Phase 2: GEMM, 32 chunk-iters = 8 n-tiles x 4 k-chunks ----
    for (int cidx = 0; cidx < 32; cidx++) {
        if (cidx + 1 < 32) {
            const char* src = (const char*)g_ehB + (size_t)(cidx + 1) * 16384;
            uint32_t dst = sb + SM_B + ((cidx + 1) & 1) * 16384;
            CP_ASYNC16(dst + tid * 32,      src + tid * 32);
            CP_ASYNC16(dst + tid * 32 + 16, src + tid * 32 + 16);
            CP_COMMIT();
            CP_WAIT(1);
        } else {
            CP_WAIT(0);
        }
        __syncthreads();

        const uint32_t abase = sb + SM_ZH + (cidx & 3) * 16384;
        const uint32_t bbase = sb + SM_B + (cidx & 1) * 16384;
#pragma unroll
        for (int k16 = 0; k16 < 4; k16++) {
            const int kb = k16 * 32;
            uint32_t afr[2][4], bfr[2][4];
            ldsm4(afr[0], abase + SW128(arow * 128 + kb + acol));
            ldsm4(afr[1], abase + SW128((arow + 16) * 128 + kb + acol));
            ldsm4(bfr[0], bbase + SW128(brow * 128 + kb + bcol));
            ldsm4(bfr[1], bbase + SW128((brow + 16) * 128 + kb + bcol));
#pragma unroll
            for (int mt = 0; mt < 2; mt++)
#pragma unroll
                for (int ni = 0; ni < 4; ni++)
                    mma16816(acc[mt][ni], afr[mt],
                             bfr[ni >> 1][(ni & 1) * 2], bfr[ni >> 1][(ni & 1) * 2 + 1]);
        }

        if ((cidx & 3) == 3) {
            // n-tile epilogue: predicated min1/min2 update (branch-free)
            const int t = cidx >> 2;
#pragma unroll
            for (int mt = 0; mt < 2; mt++)
#pragma unroll
                for (int ni = 0; ni < 4; ni++)
#pragma unroll
                    for (int e2 = 0; e2 < 4; e2++) {
                        int n = t * 128 + wn * 32 + ni * 8 + tg * 2 + (e2 & 1);
                        float d = fmaf(-2.0f, acc[mt][ni][e2], seS[n]);
                        int rr = mt * 2 + (e2 >> 1);
                        float old1 = ms1[rr];
                        ms2[rr] = fminf(ms2[rr], fmaxf(old1, d));
                        mi1[rr] = (d < old1) ? n : mi1[rr];
                        ms1[rr] = fminf(old1, d);
                        acc[mt][ni][e2] = 0.0f;
                    }
        }
        __syncthreads();
    }

    // ---- Phase 3: merge partials, flag ambiguous rows ----
    float* MS1 = (float*)(sm + SM_MS1);
    float* MS2 = (float*)(sm + SM_MS2);
    int*   MI1 = (int*)(sm + SM_MI1);
    int*   flg = (int*)(sm + SM_FLG);
    int*   cnt = (int*)(sm + SM_CNT);
    const int pid = wn * 4 + tg;
    if (tid == 0) cnt[0] = 0;
#pragma unroll
    for (int rr = 0; rr < 4; rr++) {
        int row = wm * 32 + (rr >> 1) * 16 + (rr & 1) * 8 + g;
        MS1[row * 17 + pid] = ms1[rr];
        MS2[row * 17 + pid] = ms2[rr];
        MI1[row * 17 + pid] = mi1[rr];
    }
    __syncthreads();

    if (tid < 128) {
        const int row = tid;
        float b1 = FINF; int bi = 0x7fffffff;
#pragma unroll 4
        for (int p = 0; p < 16; p++) {
            float v = MS1[row * 17 + p];
            int   ix = MI1[row * 17 + p];
            if (v < b1 || (v == b1 && ix < bi)) { b1 = v; bi = ix; }
        }
        float b2 = FINF;
#pragma unroll 4
        for (int p = 0; p < 16; p++) {
            b2 = fminf(b2, MS2[row * 17 + p]);
            float v = MS1[row * 17 + p];
            if (!(v == b1 && MI1[row * 17 + p] == bi)) b2 = fminf(b2, v);
        }
        if (b2 - b1 > MARGIN) {
            idxS[row] = bi;
        } else {
            int pos = atomicAdd(&cnt[0], 1);
            flg[pos] = row;
        }
    }
    __syncthreads();
    const int nf = cnt[0];

    // ---- exact rescan for flagged rows (batches of 16) ----
    float* zst = (float*)(sm + OV_ZST);
    float* szf = (float*)(sm + OV_SZ);
    float* bb  = (float*)(sm + OV_BB);
    unsigned long long* pb = (unsigned long long*)(sm + OV_PB);
    const int rowslot = tid >> 5, pair = tid & 31;

    for (int base = 0; base < nf; base += 16) {
        const int nb = min(16, nf - base);
        __syncthreads();
        // stage fp32 z rows
        for (int i = tid; i < nb * CDIM; i += 512) {
            int sl = i >> 8, cc = i & 255;
            zst[sl * CDIM + cc] =
                z[(((size_t)(b * CDIM + cc)) << 12) + hw0 + flg[base + sl]];
        }
        __syncthreads();
        // exact sz (serial ascending c, unfused) per flagged row
        if (tid < nb) {
            float a = 0.0f;
            for (int cc = 0; cc < CDIM; cc++) {
                float x = zst[tid * CDIM + cc];
                a = __fadd_rn(a, __fmul_rn(x, x));
            }
            szf[tid] = a;
        }
        float bd = FINF;
        int bi2 = 0x7fffffff;
        __syncthreads();

        for (int t2 = 0; t2 < 16; t2++) {
            unsigned long long acc2 = 0ull;
            for (int c = 0; c < 4; c++) {
                __syncthreads();   // previous block reads done
#pragma unroll
                for (int it = 0; it < 2; it++) {
                    int idx = tid + it * 512;   // 1024 float4 = 4096 f32
                    ((float4*)bb)[idx] =
                        ((const float4*)(g_er2 + (size_t)(t2 * 4 + c) * 4096))[idx];
                }
                __syncthreads();
                if (rowslot < nb) {
                    const float* zr = zst + rowslot * CDIM + c * 64;
                    const float* bp = bb + pair * 2;   // codes 2*pair, 2*pair+1
#pragma unroll 8
                    for (int k = 0; k < 64; k++)
                        FMA2(acc2, dup2(zr[k]), *(const unsigned long long*)(bp + k * 64));
                }
            }
            if (rowslot < nb) {
                float lo = __uint_as_float((unsigned)(acc2 & 0xffffffffu));
                float hi = __uint_as_float((unsigned)(acc2 >> 32));
                int n0 = t2 * 64 + pair * 2;
                float sz = szf[rowslot];
                float d0 = __fsub_rn(__fadd_rn(sz, seS[n0]),     __fmul_rn(2.0f, lo));
                float d1 = __fsub_rn(__fadd_rn(sz, seS[n0 + 1]), __fmul_rn(2.0f, hi));
                if (d0 < bd) { bd = d0; bi2 = n0; }        // ascending n: strict <
                if (d1 < bd) { bd = d1; bi2 = n0 + 1; }
            }
        }
        if (rowslot < nb)
            pb[rowslot * 32 + pair] =
                ((unsigned long long)__float_as_uint(bd) << 32) | (unsigned)bi2;
        __syncthreads();
        if (tid < nb) {
            unsigned long long best = ~0ull;
#pragma unroll 8
            for (int p = 0; p < 32; p++)
                best = min(best, pb[tid * 32 + p]);
            idxS[flg[base + tid]] = (int)(best & 0xffffffffu);
        }
    }
    __syncthreads();

    if (mode >= 2 && tid < 128)
        out[N_ZQ + 2 + m0 + tid] = (float)idxS[tid];

    // ---- fused gather: z from GMEM (coalesced), e from L2 ----
    {
        const int gm = tid & 127, gh = tid >> 7;   // row, column-quarter
        const int idx = idxS[gm];
        const float4* er4 = (const float4*)(cb + (size_t)idx * CDIM) + gh * 16;
        float lsum = 0.0f;
#pragma unroll 4
        for (int cq = 0; cq < 16; cq++) {
            float4 e4 = er4[cq];
            int c0 = gh * 64 + cq * 4;
            float ev[4] = {e4.x, e4.y, e4.z, e4.w};
#pragma unroll
            for (int j = 0; j < 4; j++) {
                int c = c0 + j;
                size_t zi = (((size_t)(b * CDIM + c)) << 12) + hw0 + gm;
                float zv = z[zi];
                float t  = __fsub_rn(ev[j], zv);           // e - z
                out[zi]  = __fadd_rn(zv, t);               // z + (e - z)
                lsum = __fmaf_rn(t, t, lsum);
            }
        }
        for (int o = 16; o > 0; o >>= 1)
            lsum += __shfl_down_sync(0xffffffffu, lsum, o);
        if (lane == 0) atomicAdd(&g_loss, (double)lsum);
    }
}

__global__ void finalize_kernel(float* __restrict__ out, int mode) {
    if (mode >= 1) {
        float mean = (float)(g_loss / (double)N_ZQ);
        out[N_ZQ]     = mean;          // codebook_loss
        out[N_ZQ + 1] = 0.25f * mean;  // commitment_loss = exactly 0.25 * mean
    }
}

// ---------------------------------------------------------------------------
extern "C" void kernel_launch(void* const* d_in, const int* in_sizes, int n_in,
                              void* d_out, int out_size) {
    const float* z  = (const float*)d_in[0];
    const float* cb = (const float*)d_in[1];
    float* out = (float*)d_out;

    int mode = 0;
    if (out_size >= N_ZQ + 2) mode = 1;
    if (out_size >= N_ZQ + 2 + N_VEC) mode = 2;

    cudaFuncSetAttribute(vq_main_kernel,
                         cudaFuncAttributeMaxDynamicSharedMemorySize, SM_TOT);

    cb_prep_kernel<<<KCODES, 256>>>(cb);
    vq_main_kernel<<<N_VEC / 128, 512, SM_TOT>>>(z, cb, out, mode);
    finalize_kernel<<<1, 1>>>(out, mode);
}